// round 1
// baseline (speedup 1.0000x reference)
#include <cuda_runtime.h>
#include <cuda_bf16.h>
#include <stdint.h>

#define NSUP   1280
#define NQRY   65536
#define DIN    2048
#define DEMB   1024
#define NCLS   64
#define NSTEPS 5

// ---------------- scratch (device globals; no allocation) ----------------
__device__ __nv_bfloat16 g_Wt[(size_t)DEMB * DIN];      // [DEMB][DIN]
__device__ __nv_bfloat16 g_qx[(size_t)NQRY * DIN];
__device__ __nv_bfloat16 g_sx[(size_t)NSUP * DIN];
__device__ __nv_bfloat16 g_qemb[(size_t)NQRY * DEMB];
__device__ __nv_bfloat16 g_semb[(size_t)NSUP * DEMB];
__device__ float g_qnorm[NQRY];
__device__ float g_ssum[NCLS * DEMB];
__device__ float g_scount[NCLS];
__device__ float g_qsum[NCLS * DEMB];
__device__ float g_qcount[NCLS];
__device__ __nv_bfloat16 g_pb[NCLS * DEMB];              // prototypes bf16 [NCLS][DEMB]
__device__ float g_pnorm[NCLS];
__device__ int   g_labels[NQRY];

// ---------------- small utility kernels ----------------
__global__ void k_zero(float* __restrict__ p, int n) {
    int i = blockIdx.x * blockDim.x + threadIdx.x;
    if (i < n) p[i] = 0.f;
}

__global__ void k_convert(const float* __restrict__ x, __nv_bfloat16* __restrict__ y, int n4) {
    int i = blockIdx.x * blockDim.x + threadIdx.x;
    if (i < n4) {
        float4 v = ((const float4*)x)[i];
        ((__nv_bfloat162*)y)[2 * i + 0] = __floats2bfloat162_rn(v.x, v.y);
        ((__nv_bfloat162*)y)[2 * i + 1] = __floats2bfloat162_rn(v.z, v.w);
    }
}

__global__ void k_transpose_w(const float* __restrict__ W, __nv_bfloat16* __restrict__ Wt) {
    int idx = blockIdx.x * blockDim.x + threadIdx.x;  // over DIN*DEMB
    if (idx < DIN * DEMB) {
        int k = idx / DEMB, n = idx % DEMB;
        Wt[(size_t)n * DIN + k] = __float2bfloat16(W[idx]);
    }
}

__global__ void k_rownorm(const __nv_bfloat16* __restrict__ e, float* __restrict__ o) {
    int row = blockIdx.x * 8 + (threadIdx.x >> 5);
    int lane = threadIdx.x & 31;
    const __nv_bfloat162* p = (const __nv_bfloat162*)(e + (size_t)row * DEMB);
    float s = 0.f;
#pragma unroll
    for (int j = lane; j < DEMB / 2; j += 32) {
        float2 v = __bfloat1622float2(p[j]);
        s += v.x * v.x + v.y * v.y;
    }
#pragma unroll
    for (int o2 = 16; o2; o2 >>= 1) s += __shfl_xor_sync(~0u, s, o2);
    if (!lane) o[row] = s;
}

__global__ void k_supp_stats(const __nv_bfloat16* __restrict__ semb, const int* __restrict__ lab,
                             float* __restrict__ ssum, float* __restrict__ scount) {
    int r = blockIdx.x;
    int L = lab[r];
    if (threadIdx.x == 0) atomicAdd(&scount[L], 1.0f);
    for (int c = threadIdx.x; c < DEMB; c += blockDim.x)
        atomicAdd(&ssum[L * DEMB + c], __bfloat162float(semb[(size_t)r * DEMB + c]));
}

__global__ void k_proto(const float* __restrict__ ssum, const float* __restrict__ scount,
                        const float* __restrict__ qsum, const float* __restrict__ qcount,
                        int useq, __nv_bfloat16* __restrict__ pb, float* __restrict__ pnorm) {
    int c = blockIdx.x;
    float cnt = scount[c] + (useq ? qcount[c] : 0.f);
    float inv = 1.f / fmaxf(cnt, 1.f);
    float s = 0.f;
    for (int j = threadIdx.x; j < DEMB; j += blockDim.x) {
        float p = (ssum[c * DEMB + j] + (useq ? qsum[c * DEMB + j] : 0.f)) * inv;
        __nv_bfloat16 pv = __float2bfloat16(p);
        pb[c * DEMB + j] = pv;
        float pf = __bfloat162float(pv);
        s += pf * pf;
    }
    __shared__ float red[8];
#pragma unroll
    for (int o2 = 16; o2; o2 >>= 1) s += __shfl_xor_sync(~0u, s, o2);
    if ((threadIdx.x & 31) == 0) red[threadIdx.x >> 5] = s;
    __syncthreads();
    if (threadIdx.x < 8) {
        s = red[threadIdx.x];
#pragma unroll
        for (int o2 = 4; o2; o2 >>= 1) s += __shfl_xor_sync(0xff, s, o2);
        if (threadIdx.x == 0) pnorm[c] = s;
    }
}

// segment-sum of query embeddings by label.
// Block = 128 threads = 4 warps; warp w owns a private 32-col slice (race-free).
// grid = (DEMB/128, 32); rows per block = NQRY/32 = 2048.
__global__ void __launch_bounds__(128) k_segsum(const __nv_bfloat16* __restrict__ qemb,
                                                const int* __restrict__ lab,
                                                float* __restrict__ qsum) {
    __shared__ float acc[4][NCLS][32];  // 32 KB
    int w = threadIdx.x >> 5, lane = threadIdx.x & 31;
    for (int i = threadIdx.x; i < 4 * NCLS * 32; i += 128) ((float*)acc)[i] = 0.f;
    __syncthreads();
    int col = blockIdx.x * 128 + w * 32 + lane;
    int rpb = NQRY / gridDim.y;
    int r0 = blockIdx.y * rpb;
    for (int r = r0; r < r0 + rpb; r++) {
        int L = lab[r];  // uniform per block -> broadcast
        acc[w][L][lane] += __bfloat162float(qemb[(size_t)r * DEMB + col]);
    }
    __syncthreads();
    for (int i = threadIdx.x; i < NCLS * 128; i += 128) {
        int cls = i >> 7;
        int cc = i & 127;
        atomicAdd(&qsum[cls * DEMB + blockIdx.x * 128 + cc], acc[cc >> 5][cls][cc & 31]);
    }
}

// ---------------- bf16 tensor-core GEMM (mma.sync m16n8k16) ----------------
// C[M,N] = A[M,K] @ B[N,K]^T   (A row-major, B stored [N][K] row-major)
// MODE 0: out_bf16 = C + bias[n]          (embedding)
// MODE 1: labels[m] = argmin_n (pnorm[n] - 2*C), qcount histogram  (transductive step)
// MODE 2: outf[m*NCLS+n] = -sqrt(max(qnorm[m]+pnorm[n]-2*C, 1e-12))  (logits)
#define CP_ASYNC(dst, src) asm volatile("cp.async.cg.shared.global [%0], [%1], 16;\n" ::"r"(dst), "l"(src))

template <int BM, int BN, int BK, int WMT, int WNT, int MODE>
__global__ void __launch_bounds__(WMT* WNT * 32) k_gemm(
    const __nv_bfloat16* __restrict__ A, const __nv_bfloat16* __restrict__ B, int K,
    const float* __restrict__ bias, __nv_bfloat16* __restrict__ outb, int ldo,
    const float* __restrict__ pnorm, int* __restrict__ labels, float* __restrict__ qcount,
    const float* __restrict__ qnorm, float* __restrict__ outf) {
    constexpr int NT = WMT * WNT * 32;
    constexpr int LDA = BK + 8;     // halves; +16B pad -> conflict-free ldmatrix
    constexpr int WM = BM / WMT, WN = BN / WNT;
    constexpr int MF = WM / 16, NF = WN / 8;
    constexpr int CPR = BK / 8;     // 16B chunks per row
    constexpr int AIT = BM * CPR / NT;
    constexpr int BIT = BN * CPR / NT;

    extern __shared__ char smem_raw[];
    uint32_t sA = (uint32_t)__cvta_generic_to_shared(smem_raw);
    uint32_t sB = sA + 2u * BM * LDA * 2u;

    const int tid = threadIdx.x;
    const int warp = tid >> 5, lane = tid & 31;
    const int wm = (warp / WNT) * WM, wn = (warp % WNT) * WN;
    const int bm0 = blockIdx.y * BM, bn0 = blockIdx.x * BN;

    const __nv_bfloat16* Ab = A + (size_t)bm0 * K;
    const __nv_bfloat16* Bb = B + (size_t)bn0 * K;

    float acc[MF][NF][4];
#pragma unroll
    for (int i = 0; i < MF; i++)
#pragma unroll
        for (int j = 0; j < NF; j++)
#pragma unroll
            for (int q = 0; q < 4; q++) acc[i][j][q] = 0.f;

    const int KT = K / BK;

    auto load = [&](int kt, int s) {
#pragma unroll
        for (int i = 0; i < AIT; i++) {
            int idx = tid + i * NT;
            int row = idx / CPR, ch = idx % CPR;
            CP_ASYNC(sA + (uint32_t)((s * BM * LDA + row * LDA + ch * 8) * 2),
                     Ab + (size_t)row * K + (size_t)kt * BK + ch * 8);
        }
#pragma unroll
        for (int i = 0; i < BIT; i++) {
            int idx = tid + i * NT;
            int row = idx / CPR, ch = idx % CPR;
            CP_ASYNC(sB + (uint32_t)((s * BN * LDA + row * LDA + ch * 8) * 2),
                     Bb + (size_t)row * K + (size_t)kt * BK + ch * 8);
        }
        asm volatile("cp.async.commit_group;\n");
    };

    load(0, 0);
    for (int kt = 0; kt < KT; kt++) {
        if (kt + 1 < KT) {
            load(kt + 1, (kt + 1) & 1);
            asm volatile("cp.async.wait_group 1;\n");
        } else {
            asm volatile("cp.async.wait_group 0;\n");
        }
        __syncthreads();
        uint32_t aBase = sA + (uint32_t)(((kt & 1) * BM * LDA) * 2);
        uint32_t bBase = sB + (uint32_t)(((kt & 1) * BN * LDA) * 2);
#pragma unroll
        for (int ks = 0; ks < BK / 16; ks++) {
            uint32_t af[MF][4];
#pragma unroll
            for (int mi = 0; mi < MF; mi++) {
                int row = wm + mi * 16 + (lane & 15);
                int colh = ks * 16 + (lane >> 4) * 8;
                uint32_t ad = aBase + (uint32_t)((row * LDA + colh) * 2);
                asm volatile("ldmatrix.sync.aligned.m8n8.x4.shared.b16 {%0,%1,%2,%3},[%4];"
                             : "=r"(af[mi][0]), "=r"(af[mi][1]), "=r"(af[mi][2]), "=r"(af[mi][3])
                             : "r"(ad));
            }
            uint32_t bfr[NF][2];
#pragma unroll
            for (int ni2 = 0; ni2 < NF / 2; ni2++) {
                int nrow = wn + ni2 * 16 + (lane & 7) + ((lane >> 4) << 3);
                int colh = ks * 16 + (((lane >> 3) & 1) << 3);
                uint32_t bd = bBase + (uint32_t)((nrow * LDA + colh) * 2);
                uint32_t r0, r1, r2, r3;
                asm volatile("ldmatrix.sync.aligned.m8n8.x4.shared.b16 {%0,%1,%2,%3},[%4];"
                             : "=r"(r0), "=r"(r1), "=r"(r2), "=r"(r3)
                             : "r"(bd));
                bfr[2 * ni2][0] = r0; bfr[2 * ni2][1] = r1;
                bfr[2 * ni2 + 1][0] = r2; bfr[2 * ni2 + 1][1] = r3;
            }
#pragma unroll
            for (int mi = 0; mi < MF; mi++)
#pragma unroll
                for (int ni = 0; ni < NF; ni++)
                    asm volatile(
                        "mma.sync.aligned.m16n8k16.row.col.f32.bf16.bf16.f32 "
                        "{%0,%1,%2,%3},{%4,%5,%6,%7},{%8,%9},{%0,%1,%2,%3};"
                        : "+f"(acc[mi][ni][0]), "+f"(acc[mi][ni][1]),
                          "+f"(acc[mi][ni][2]), "+f"(acc[mi][ni][3])
                        : "r"(af[mi][0]), "r"(af[mi][1]), "r"(af[mi][2]), "r"(af[mi][3]),
                          "r"(bfr[ni][0]), "r"(bfr[ni][1]));
        }
        __syncthreads();
    }

    if (MODE == 0) {
#pragma unroll
        for (int mi = 0; mi < MF; mi++) {
            int row = bm0 + wm + mi * 16 + (lane >> 2);
#pragma unroll
            for (int ni = 0; ni < NF; ni++) {
                int col = bn0 + wn + ni * 8 + (lane & 3) * 2;
                float b0v = bias[col], b1v = bias[col + 1];
#pragma unroll
                for (int h = 0; h < 2; h++) {
                    int rr = row + h * 8;
                    __nv_bfloat162 p = __floats2bfloat162_rn(acc[mi][ni][2 * h] + b0v,
                                                             acc[mi][ni][2 * h + 1] + b1v);
                    *(__nv_bfloat162*)(outb + (size_t)rr * ldo + col) = p;
                }
            }
        }
    } else if (MODE == 1) {
        float bv[MF][2];
        int bc[MF][2];
#pragma unroll
        for (int mi = 0; mi < MF; mi++)
#pragma unroll
            for (int h = 0; h < 2; h++) { bv[mi][h] = 1e30f; bc[mi][h] = 0; }
#pragma unroll
        for (int mi = 0; mi < MF; mi++)
#pragma unroll
            for (int ni = 0; ni < NF; ni++)
#pragma unroll
                for (int h = 0; h < 2; h++)
#pragma unroll
                    for (int j = 0; j < 2; j++) {
                        int c = wn + ni * 8 + (lane & 3) * 2 + j;
                        float m = pnorm[c] - 2.f * acc[mi][ni][2 * h + j];
                        if (m < bv[mi][h]) { bv[mi][h] = m; bc[mi][h] = c; }
                    }
#pragma unroll
        for (int off = 1; off <= 2; off <<= 1)
#pragma unroll
            for (int mi = 0; mi < MF; mi++)
#pragma unroll
                for (int h = 0; h < 2; h++) {
                    float ov = __shfl_xor_sync(~0u, bv[mi][h], off);
                    int oc = __shfl_xor_sync(~0u, bc[mi][h], off);
                    if (ov < bv[mi][h] || (ov == bv[mi][h] && oc < bc[mi][h])) {
                        bv[mi][h] = ov; bc[mi][h] = oc;
                    }
                }
        float* redv = (float*)smem_raw;
        int* redi = (int*)smem_raw + BM * WNT;
        __shared__ int hist[NCLS];
        if (tid < NCLS) hist[tid] = 0;
        if ((lane & 3) == 0) {
#pragma unroll
            for (int mi = 0; mi < MF; mi++)
#pragma unroll
                for (int h = 0; h < 2; h++) {
                    int r = wm + mi * 16 + (lane >> 2) + 8 * h;
                    redv[r * WNT + (warp % WNT)] = bv[mi][h];
                    redi[r * WNT + (warp % WNT)] = bc[mi][h];
                }
        }
        __syncthreads();
        if (tid < BM) {
            float v = redv[tid * WNT];
            int cbest = redi[tid * WNT];
#pragma unroll
            for (int w2 = 1; w2 < WNT; w2++) {
                float ov = redv[tid * WNT + w2];
                int oc = redi[tid * WNT + w2];
                if (ov < v || (ov == v && oc < cbest)) { v = ov; cbest = oc; }
            }
            labels[bm0 + tid] = cbest;
            atomicAdd(&hist[cbest], 1);
        }
        __syncthreads();
        if (tid < NCLS) atomicAdd(&qcount[tid], (float)hist[tid]);
    } else {  // MODE 2
#pragma unroll
        for (int mi = 0; mi < MF; mi++) {
            int row = bm0 + wm + mi * 16 + (lane >> 2);
#pragma unroll
            for (int h = 0; h < 2; h++) {
                int rr = row + 8 * h;
                float qn = qnorm[rr];
#pragma unroll
                for (int ni = 0; ni < NF; ni++)
#pragma unroll
                    for (int j = 0; j < 2; j++) {
                        int c = wn + ni * 8 + (lane & 3) * 2 + j;
                        float d2 = qn + pnorm[c] - 2.f * acc[mi][ni][2 * h + j];
                        outf[(size_t)rr * NCLS + c] = -sqrtf(fmaxf(d2, 1e-12f));
                    }
            }
        }
    }
}

// ---------------- host orchestration ----------------
extern "C" void kernel_launch(void* const* d_in, const int* in_sizes, int n_in,
                              void* d_out, int out_size) {
    (void)in_sizes; (void)n_in; (void)out_size;
    const float* support = (const float*)d_in[0];
    const float* query = (const float*)d_in[1];
    const int* slab = (const int*)d_in[2];
    const float* W = (const float*)d_in[3];
    const float* bias = (const float*)d_in[4];
    float* out = (float*)d_out;

    __nv_bfloat16 *Wt, *qx, *sx, *qemb, *semb, *pb;
    float *qnorm, *ssum, *scount, *qsum, *qcount, *pnorm;
    int* labels;
    cudaGetSymbolAddress((void**)&Wt, g_Wt);
    cudaGetSymbolAddress((void**)&qx, g_qx);
    cudaGetSymbolAddress((void**)&sx, g_sx);
    cudaGetSymbolAddress((void**)&qemb, g_qemb);
    cudaGetSymbolAddress((void**)&semb, g_semb);
    cudaGetSymbolAddress((void**)&qnorm, g_qnorm);
    cudaGetSymbolAddress((void**)&ssum, g_ssum);
    cudaGetSymbolAddress((void**)&scount, g_scount);
    cudaGetSymbolAddress((void**)&qsum, g_qsum);
    cudaGetSymbolAddress((void**)&qcount, g_qcount);
    cudaGetSymbolAddress((void**)&pb, g_pb);
    cudaGetSymbolAddress((void**)&pnorm, g_pnorm);
    cudaGetSymbolAddress((void**)&labels, g_labels);

    // conversions
    k_transpose_w<<<(DIN * DEMB + 255) / 256, 256>>>(W, Wt);
    k_convert<<<(NSUP * DIN / 4 + 255) / 256, 256>>>(support, sx, NSUP * DIN / 4);
    k_convert<<<(NQRY * DIN / 4 + 255) / 256, 256>>>(query, qx, NQRY * DIN / 4);

    // embeddings (bf16 out)
    k_gemm<128, 128, 32, 2, 4, 0><<<dim3(DEMB / 128, NSUP / 128), 256, 40960>>>(
        sx, Wt, DIN, bias, semb, DEMB, nullptr, nullptr, nullptr, nullptr, nullptr);
    k_gemm<128, 128, 32, 2, 4, 0><<<dim3(DEMB / 128, NQRY / 128), 256, 40960>>>(
        qx, Wt, DIN, bias, qemb, DEMB, nullptr, nullptr, nullptr, nullptr, nullptr);

    k_rownorm<<<NQRY / 8, 256>>>(qemb, qnorm);

    // support class sums + counts -> initial prototypes
    k_zero<<<(NCLS * DEMB + 255) / 256, 256>>>(ssum, NCLS * DEMB);
    k_zero<<<1, 64>>>(scount, NCLS);
    k_supp_stats<<<NSUP, 256>>>(semb, slab, ssum, scount);
    k_proto<<<NCLS, 256>>>(ssum, scount, nullptr, nullptr, 0, pb, pnorm);

    for (int s = 0; s < NSTEPS; s++) {
        k_zero<<<(NCLS * DEMB + 255) / 256, 256>>>(qsum, NCLS * DEMB);
        k_zero<<<1, 64>>>(qcount, NCLS);
        k_gemm<128, 64, 32, 4, 2, 1><<<dim3(1, NQRY / 128), 256, 30720>>>(
            qemb, pb, DEMB, nullptr, nullptr, 0, pnorm, labels, qcount, nullptr, nullptr);
        k_segsum<<<dim3(DEMB / 128, 32), 128>>>(qemb, labels, qsum);
        k_proto<<<NCLS, 256>>>(ssum, scount, qsum, qcount, 1, pb, pnorm);
    }

    // final logits
    k_gemm<128, 64, 32, 4, 2, 2><<<dim3(1, NQRY / 128), 256, 30720>>>(
        qemb, pb, DEMB, nullptr, nullptr, 0, pnorm, nullptr, nullptr, qnorm, out);
}

// round 3
// speedup vs baseline: 1.1063x; 1.1063x over previous
#include <cuda_runtime.h>
#include <cuda_bf16.h>
#include <stdint.h>

#define NSUP   1280
#define NQRY   65536
#define DIN    2048
#define DEMB   1024
#define NCLS   64
#define NSTEPS 5

// ---------------- scratch (device globals; no allocation) ----------------
__device__ __align__(256) __nv_bfloat16 g_Wt[(size_t)DEMB * DIN];      // [DEMB][DIN]
__device__ __align__(256) __nv_bfloat16 g_qx[(size_t)NQRY * DIN];
__device__ __align__(256) __nv_bfloat16 g_sx[(size_t)NSUP * DIN];
__device__ __align__(256) __nv_bfloat16 g_qemb[(size_t)NQRY * DEMB];
__device__ __align__(256) __nv_bfloat16 g_semb[(size_t)NSUP * DEMB];
__device__ float g_qnorm[NQRY];
__device__ float g_ssum[NCLS * DEMB];
__device__ float g_scount[NCLS];
__device__ float g_qsum[NCLS * DEMB];
__device__ float g_qcount[NCLS];
__device__ __align__(256) __nv_bfloat16 g_pb[NCLS * DEMB];             // prototypes bf16
__device__ float g_pnorm[NCLS];
__device__ int   g_labels[NQRY];

// ---------------- small utility kernels ----------------
__global__ void k_zero(float* __restrict__ p, int n) {
    int i = blockIdx.x * blockDim.x + threadIdx.x;
    if (i < n) p[i] = 0.f;
}

__global__ void k_convert(const float* __restrict__ x, __nv_bfloat16* __restrict__ y, int n4) {
    int i = blockIdx.x * blockDim.x + threadIdx.x;
    if (i < n4) {
        float4 v = ((const float4*)x)[i];
        ((__nv_bfloat162*)y)[2 * i + 0] = __floats2bfloat162_rn(v.x, v.y);
        ((__nv_bfloat162*)y)[2 * i + 1] = __floats2bfloat162_rn(v.z, v.w);
    }
}

// tiled transpose: W [DIN][DEMB] f32 -> Wt [DEMB][DIN] bf16
__global__ void k_transpose_w(const float* __restrict__ W, __nv_bfloat16* __restrict__ Wt) {
    __shared__ float tile[32][33];
    int n0 = blockIdx.x * 32, k0 = blockIdx.y * 32;
#pragma unroll
    for (int i = 0; i < 4; i++) {
        int k = k0 + threadIdx.y + i * 8;
        tile[threadIdx.y + i * 8][threadIdx.x] = W[(size_t)k * DEMB + n0 + threadIdx.x];
    }
    __syncthreads();
#pragma unroll
    for (int i = 0; i < 4; i++) {
        int n = n0 + threadIdx.y + i * 8;
        Wt[(size_t)n * DIN + k0 + threadIdx.x] =
            __float2bfloat16(tile[threadIdx.x][threadIdx.y + i * 8]);
    }
}

__global__ void k_rownorm(const __nv_bfloat16* __restrict__ e, float* __restrict__ o) {
    int row = blockIdx.x * 8 + (threadIdx.x >> 5);
    int lane = threadIdx.x & 31;
    const __nv_bfloat162* p = (const __nv_bfloat162*)(e + (size_t)row * DEMB);
    float s = 0.f;
#pragma unroll
    for (int j = lane; j < DEMB / 2; j += 32) {
        float2 v = __bfloat1622float2(p[j]);
        s += v.x * v.x + v.y * v.y;
    }
#pragma unroll
    for (int o2 = 16; o2; o2 >>= 1) s += __shfl_xor_sync(~0u, s, o2);
    if (!lane) o[row] = s;
}

__global__ void k_supp_stats(const __nv_bfloat16* __restrict__ semb, const int* __restrict__ lab,
                             float* __restrict__ ssum, float* __restrict__ scount) {
    int r = blockIdx.x;
    int L = lab[r];
    if (threadIdx.x == 0) atomicAdd(&scount[L], 1.0f);
    for (int c = threadIdx.x; c < DEMB; c += blockDim.x)
        atomicAdd(&ssum[L * DEMB + c], __bfloat162float(semb[(size_t)r * DEMB + c]));
}

__global__ void k_proto(const float* __restrict__ ssum, const float* __restrict__ scount,
                        const float* __restrict__ qsum, const float* __restrict__ qcount,
                        int useq, __nv_bfloat16* __restrict__ pb, float* __restrict__ pnorm) {
    int c = blockIdx.x;
    float cnt = scount[c] + (useq ? qcount[c] : 0.f);
    float inv = 1.f / fmaxf(cnt, 1.f);
    float s = 0.f;
    for (int j = threadIdx.x; j < DEMB; j += blockDim.x) {
        float p = (ssum[c * DEMB + j] + (useq ? qsum[c * DEMB + j] : 0.f)) * inv;
        __nv_bfloat16 pv = __float2bfloat16(p);
        pb[c * DEMB + j] = pv;
        float pf = __bfloat162float(pv);
        s += pf * pf;
    }
    __shared__ float red[8];
#pragma unroll
    for (int o2 = 16; o2; o2 >>= 1) s += __shfl_xor_sync(~0u, s, o2);
    if ((threadIdx.x & 31) == 0) red[threadIdx.x >> 5] = s;
    __syncthreads();
    if (threadIdx.x < 8) {
        s = red[threadIdx.x];
#pragma unroll
        for (int o2 = 4; o2; o2 >>= 1) s += __shfl_xor_sync(0xff, s, o2);
        if (threadIdx.x == 0) pnorm[c] = s;
    }
}

// segment-sum of query embeddings by label (race-free smem slices).
__global__ void __launch_bounds__(128) k_segsum(const __nv_bfloat16* __restrict__ qemb,
                                                const int* __restrict__ lab,
                                                float* __restrict__ qsum) {
    __shared__ float acc[4][NCLS][32];  // 32 KB
    int w = threadIdx.x >> 5, lane = threadIdx.x & 31;
    for (int i = threadIdx.x; i < 4 * NCLS * 32; i += 128) ((float*)acc)[i] = 0.f;
    __syncthreads();
    int col = blockIdx.x * 128 + w * 32 + lane;
    int rpb = NQRY / gridDim.y;
    int r0 = blockIdx.y * rpb;
    for (int r = r0; r < r0 + rpb; r++) {
        int L = lab[r];
        acc[w][L][lane] += __bfloat162float(qemb[(size_t)r * DEMB + col]);
    }
    __syncthreads();
    for (int i = threadIdx.x; i < NCLS * 128; i += 128) {
        int cls = i >> 7;
        int cc = i & 127;
        atomicAdd(&qsum[cls * DEMB + blockIdx.x * 128 + cc], acc[cc >> 5][cls][cc & 31]);
    }
}

// ---------------- bf16 HMMA GEMM (mma.sync m16n8k16), BK=64, 3-stage, swizzled ----------------
// C[M,N] = A[M,K] @ B[N,K]^T
// MODE 0: out_bf16 = C + bias[n]
// MODE 1: labels[m] = argmin_n (pnorm[n] - 2*C), qcount histogram
// MODE 2: outf[m*NCLS+n] = -sqrt(max(qnorm[m]+pnorm[n]-2*C, 1e-12))
#define CP_ASYNC(dst, src) asm volatile("cp.async.cg.shared.global [%0], [%1], 16;\n" ::"r"(dst), "l"(src))

template <int BM, int BN, int WMT, int WNT, int MODE>
__global__ void __launch_bounds__(WMT* WNT * 32, 1) k_gemm(
    const __nv_bfloat16* __restrict__ A, const __nv_bfloat16* __restrict__ B, int K,
    const float* __restrict__ bias, __nv_bfloat16* __restrict__ outb, int ldo,
    const float* __restrict__ pnorm, int* __restrict__ labels, float* __restrict__ qcount,
    const float* __restrict__ qnorm, float* __restrict__ outf) {
    constexpr int NT = WMT * WNT * 32;
    constexpr int WM = BM / WMT, WN = BN / WNT;
    constexpr int MF = WM / 16, NF = WN / 8;
    constexpr int AIT = BM * 8 / NT;   // 16B chunks per thread (A)
    constexpr int BIT = BN * 8 / NT;
    constexpr uint32_t STAGE = (BM + BN) * 128;

    extern __shared__ char smem_raw[];
    uint32_t sbase = (uint32_t)__cvta_generic_to_shared(smem_raw);

    const int tid = threadIdx.x;
    const int warp = tid >> 5, lane = tid & 31;
    const int wm = (warp / WNT) * WM, wn = (warp % WNT) * WN;
    const int bm0 = blockIdx.y * BM, bn0 = blockIdx.x * BN;

    const __nv_bfloat16* Ab = A + (size_t)bm0 * K;
    const __nv_bfloat16* Bb = B + (size_t)bn0 * K;

    float acc[MF][NF][4];
#pragma unroll
    for (int i = 0; i < MF; i++)
#pragma unroll
        for (int j = 0; j < NF; j++)
#pragma unroll
            for (int q = 0; q < 4; q++) acc[i][j][q] = 0.f;

    const int KT = K >> 6;  // BK=64

    auto load = [&](int kt) {
        uint32_t sA = sbase + (kt % 3) * STAGE;
        uint32_t sB = sA + (uint32_t)BM * 128u;
        const __nv_bfloat16* Ap = Ab + (size_t)kt * 64;
        const __nv_bfloat16* Bp = Bb + (size_t)kt * 64;
#pragma unroll
        for (int i = 0; i < AIT; i++) {
            int idx = tid + i * NT;
            int r = idx >> 3, c = idx & 7;
            CP_ASYNC(sA + (uint32_t)(r * 128 + ((c ^ (r & 7)) * 16)), Ap + (size_t)r * K + c * 8);
        }
#pragma unroll
        for (int i = 0; i < BIT; i++) {
            int idx = tid + i * NT;
            int r = idx >> 3, c = idx & 7;
            CP_ASYNC(sB + (uint32_t)(r * 128 + ((c ^ (r & 7)) * 16)), Bp + (size_t)r * K + c * 8);
        }
        asm volatile("cp.async.commit_group;\n");
    };

    load(0);
    load(1);
    for (int kt = 0; kt < KT; kt++) {
        if (kt < KT - 1)
            asm volatile("cp.async.wait_group 1;\n" ::: "memory");
        else
            asm volatile("cp.async.wait_group 0;\n" ::: "memory");
        __syncthreads();
        uint32_t aBase = sbase + (kt % 3) * STAGE;
        uint32_t bBase = aBase + (uint32_t)BM * 128u;
#pragma unroll
        for (int ks = 0; ks < 4; ks++) {
            uint32_t af[MF][4];
#pragma unroll
            for (int mi = 0; mi < MF; mi++) {
                int row = wm + mi * 16 + (lane & 15);
                int ch = (ks * 2 + (lane >> 4)) ^ (row & 7);
                uint32_t adr = aBase + (uint32_t)(row * 128 + ch * 16);
                asm volatile("ldmatrix.sync.aligned.m8n8.x4.shared.b16 {%0,%1,%2,%3},[%4];"
                             : "=r"(af[mi][0]), "=r"(af[mi][1]), "=r"(af[mi][2]), "=r"(af[mi][3])
                             : "r"(adr));
            }
            uint32_t bfr[NF][2];
#pragma unroll
            for (int ni2 = 0; ni2 < NF / 2; ni2++) {
                int nrow = wn + ni2 * 16 + (lane & 7) + ((lane >> 4) << 3);
                int ch = (ks * 2 + ((lane >> 3) & 1)) ^ (nrow & 7);
                uint32_t bd = bBase + (uint32_t)(nrow * 128 + ch * 16);
                uint32_t r0, r1, r2, r3;
                asm volatile("ldmatrix.sync.aligned.m8n8.x4.shared.b16 {%0,%1,%2,%3},[%4];"
                             : "=r"(r0), "=r"(r1), "=r"(r2), "=r"(r3)
                             : "r"(bd));
                bfr[2 * ni2][0] = r0; bfr[2 * ni2][1] = r1;
                bfr[2 * ni2 + 1][0] = r2; bfr[2 * ni2 + 1][1] = r3;
            }
#pragma unroll
            for (int mi = 0; mi < MF; mi++)
#pragma unroll
                for (int ni = 0; ni < NF; ni++)
                    asm volatile(
                        "mma.sync.aligned.m16n8k16.row.col.f32.bf16.bf16.f32 "
                        "{%0,%1,%2,%3},{%4,%5,%6,%7},{%8,%9},{%0,%1,%2,%3};"
                        : "+f"(acc[mi][ni][0]), "+f"(acc[mi][ni][1]),
                          "+f"(acc[mi][ni][2]), "+f"(acc[mi][ni][3])
                        : "r"(af[mi][0]), "r"(af[mi][1]), "r"(af[mi][2]), "r"(af[mi][3]),
                          "r"(bfr[ni][0]), "r"(bfr[ni][1]));
        }
        __syncthreads();
        if (kt + 2 < KT) load(kt + 2);
    }

    if (MODE == 0) {
#pragma unroll
        for (int mi = 0; mi < MF; mi++) {
            int row = bm0 + wm + mi * 16 + (lane >> 2);
#pragma unroll
            for (int ni = 0; ni < NF; ni++) {
                int col = bn0 + wn + ni * 8 + (lane & 3) * 2;
                float b0v = __ldg(&bias[col]), b1v = __ldg(&bias[col + 1]);
#pragma unroll
                for (int h = 0; h < 2; h++) {
                    int rr = row + h * 8;
                    __nv_bfloat162 p = __floats2bfloat162_rn(acc[mi][ni][2 * h] + b0v,
                                                             acc[mi][ni][2 * h + 1] + b1v);
                    *(__nv_bfloat162*)(outb + (size_t)rr * ldo + col) = p;
                }
            }
        }
    } else if (MODE == 1) {
        float bv[MF][2];
        int bc[MF][2];
#pragma unroll
        for (int mi = 0; mi < MF; mi++)
#pragma unroll
            for (int h = 0; h < 2; h++) { bv[mi][h] = 1e30f; bc[mi][h] = 0; }
#pragma unroll
        for (int mi = 0; mi < MF; mi++)
#pragma unroll
            for (int ni = 0; ni < NF; ni++)
#pragma unroll
                for (int h = 0; h < 2; h++)
#pragma unroll
                    for (int j = 0; j < 2; j++) {
                        int c = wn + ni * 8 + (lane & 3) * 2 + j;
                        float m = pnorm[c] - 2.f * acc[mi][ni][2 * h + j];
                        if (m < bv[mi][h]) { bv[mi][h] = m; bc[mi][h] = c; }
                    }
#pragma unroll
        for (int off = 1; off <= 2; off <<= 1)
#pragma unroll
            for (int mi = 0; mi < MF; mi++)
#pragma unroll
                for (int h = 0; h < 2; h++) {
                    float ov = __shfl_xor_sync(~0u, bv[mi][h], off);
                    int oc = __shfl_xor_sync(~0u, bc[mi][h], off);
                    if (ov < bv[mi][h] || (ov == bv[mi][h] && oc < bc[mi][h])) {
                        bv[mi][h] = ov; bc[mi][h] = oc;
                    }
                }
        float* redv = (float*)smem_raw;
        int* redi = (int*)smem_raw + BM * WNT;
        __shared__ int hist[NCLS];
        if (tid < NCLS) hist[tid] = 0;
        if ((lane & 3) == 0) {
#pragma unroll
            for (int mi = 0; mi < MF; mi++)
#pragma unroll
                for (int h = 0; h < 2; h++) {
                    int r = wm + mi * 16 + (lane >> 2) + 8 * h;
                    redv[r * WNT + (warp % WNT)] = bv[mi][h];
                    redi[r * WNT + (warp % WNT)] = bc[mi][h];
                }
        }
        __syncthreads();
        if (tid < BM) {
            float v = redv[tid * WNT];
            int cbest = redi[tid * WNT];
#pragma unroll
            for (int w2 = 1; w2 < WNT; w2++) {
                float ov = redv[tid * WNT + w2];
                int oc = redi[tid * WNT + w2];
                if (ov < v || (ov == v && oc < cbest)) { v = ov; cbest = oc; }
            }
            labels[bm0 + tid] = cbest;
            atomicAdd(&hist[cbest], 1);
        }
        __syncthreads();
        if (tid < NCLS) atomicAdd(&qcount[tid], (float)hist[tid]);
    } else {  // MODE 2
#pragma unroll
        for (int mi = 0; mi < MF; mi++) {
            int row = bm0 + wm + mi * 16 + (lane >> 2);
#pragma unroll
            for (int h = 0; h < 2; h++) {
                int rr = row + 8 * h;
                float qn = qnorm[rr];
#pragma unroll
                for (int ni = 0; ni < NF; ni++)
#pragma unroll
                    for (int j = 0; j < 2; j++) {
                        int c = wn + ni * 8 + (lane & 3) * 2 + j;
                        float d2 = qn + pnorm[c] - 2.f * acc[mi][ni][2 * h + j];
                        outf[(size_t)rr * NCLS + c] = -sqrtf(fmaxf(d2, 1e-12f));
                    }
            }
        }
    }
}

// ---------------- host orchestration ----------------
extern "C" void kernel_launch(void* const* d_in, const int* in_sizes, int n_in,
                              void* d_out, int out_size) {
    (void)in_sizes; (void)n_in; (void)out_size;
    const float* support = (const float*)d_in[0];
    const float* query = (const float*)d_in[1];
    const int* slab = (const int*)d_in[2];
    const float* W = (const float*)d_in[3];
    const float* bias = (const float*)d_in[4];
    float* out = (float*)d_out;

    __nv_bfloat16 *Wt, *qx, *sx, *qemb, *semb, *pb;
    float *qnorm, *ssum, *scount, *qsum, *qcount, *pnorm;
    int* labels;
    cudaGetSymbolAddress((void**)&Wt, g_Wt);
    cudaGetSymbolAddress((void**)&qx, g_qx);
    cudaGetSymbolAddress((void**)&sx, g_sx);
    cudaGetSymbolAddress((void**)&qemb, g_qemb);
    cudaGetSymbolAddress((void**)&semb, g_semb);
    cudaGetSymbolAddress((void**)&qnorm, g_qnorm);
    cudaGetSymbolAddress((void**)&ssum, g_ssum);
    cudaGetSymbolAddress((void**)&scount, g_scount);
    cudaGetSymbolAddress((void**)&qsum, g_qsum);
    cudaGetSymbolAddress((void**)&qcount, g_qcount);
    cudaGetSymbolAddress((void**)&pb, g_pb);
    cudaGetSymbolAddress((void**)&pnorm, g_pnorm);
    cudaGetSymbolAddress((void**)&labels, g_labels);

    const int SMEM_BIG = 3 * (128 + 256) * 128;   // 147456
    const int SMEM_SML = 3 * (128 + 64) * 128;    // 73728
    cudaFuncSetAttribute(k_gemm<128, 256, 2, 4, 0>, cudaFuncAttributeMaxDynamicSharedMemorySize, SMEM_BIG);
    cudaFuncSetAttribute(k_gemm<128, 64, 4, 2, 1>, cudaFuncAttributeMaxDynamicSharedMemorySize, SMEM_SML);
    cudaFuncSetAttribute(k_gemm<128, 64, 4, 2, 2>, cudaFuncAttributeMaxDynamicSharedMemorySize, SMEM_SML);

    // conversions
    k_transpose_w<<<dim3(DEMB / 32, DIN / 32), dim3(32, 8)>>>(W, Wt);
    k_convert<<<(NSUP * DIN / 4 + 255) / 256, 256>>>(support, sx, NSUP * DIN / 4);
    k_convert<<<(NQRY * DIN / 4 + 255) / 256, 256>>>(query, qx, NQRY * DIN / 4);

    // embeddings (bf16 out, bias fused)
    k_gemm<128, 256, 2, 4, 0><<<dim3(DEMB / 256, NSUP / 128), 256, SMEM_BIG>>>(
        sx, Wt, DIN, bias, semb, DEMB, nullptr, nullptr, nullptr, nullptr, nullptr);
    k_gemm<128, 256, 2, 4, 0><<<dim3(DEMB / 256, NQRY / 128), 256, SMEM_BIG>>>(
        qx, Wt, DIN, bias, qemb, DEMB, nullptr, nullptr, nullptr, nullptr, nullptr);

    k_rownorm<<<NQRY / 8, 256>>>(qemb, qnorm);

    // support class sums + counts -> initial prototypes
    k_zero<<<(NCLS * DEMB + 255) / 256, 256>>>(ssum, NCLS * DEMB);
    k_zero<<<1, 64>>>(scount, NCLS);
    k_supp_stats<<<NSUP, 256>>>(semb, slab, ssum, scount);
    k_proto<<<NCLS, 256>>>(ssum, scount, nullptr, nullptr, 0, pb, pnorm);

    for (int s = 0; s < NSTEPS; s++) {
        k_zero<<<(NCLS * DEMB + 255) / 256, 256>>>(qsum, NCLS * DEMB);
        k_zero<<<1, 64>>>(qcount, NCLS);
        k_gemm<128, 64, 4, 2, 1><<<dim3(1, NQRY / 128), 256, SMEM_SML>>>(
            qemb, pb, DEMB, nullptr, nullptr, 0, pnorm, labels, qcount, nullptr, nullptr);
        k_segsum<<<dim3(DEMB / 128, 32), 128>>>(qemb, labels, qsum);
        k_proto<<<NCLS, 256>>>(ssum, scount, qsum, qcount, 1, pb, pnorm);
    }

    // final logits
    k_gemm<128, 64, 4, 2, 2><<<dim3(1, NQRY / 128), 256, SMEM_SML>>>(
        qemb, pb, DEMB, nullptr, nullptr, 0, pnorm, nullptr, nullptr, qnorm, out);
}

// round 4
// speedup vs baseline: 1.1949x; 1.0800x over previous
#include <cuda_runtime.h>
#include <cuda_bf16.h>
#include <stdint.h>

#define NSUP   1280
#define NQRY   65536
#define DIN    2048
#define DEMB   1024
#define NCLS   64
#define NSTEPS 5

// ---------------- scratch (device globals; no allocation) ----------------
__device__ __align__(256) __nv_bfloat16 g_Wt[(size_t)DEMB * DIN];      // [DEMB][DIN]
__device__ __align__(256) __nv_bfloat16 g_qx[(size_t)NQRY * DIN];
__device__ __align__(256) __nv_bfloat16 g_sx[(size_t)NSUP * DIN];
__device__ __align__(256) __nv_bfloat16 g_qemb[(size_t)NQRY * DEMB];
__device__ __align__(256) __nv_bfloat16 g_semb[(size_t)NSUP * DEMB];
__device__ float g_qnorm[NQRY];
__device__ float g_ssum[NCLS * DEMB];
__device__ float g_scount[NCLS];
__device__ float g_qsum[NCLS * DEMB];
__device__ float g_qcount[NCLS];
__device__ __align__(256) __nv_bfloat16 g_pb[NCLS * DEMB];             // prototypes bf16
__device__ float g_pnorm[NCLS];
__device__ int   g_labels[NQRY];

// ---------------- small utility kernels ----------------
__global__ void k_zero(float* __restrict__ p, int n) {
    int i = blockIdx.x * blockDim.x + threadIdx.x;
    if (i < n) p[i] = 0.f;
}

__global__ void k_convert(const float* __restrict__ x, __nv_bfloat16* __restrict__ y, int n4) {
    int i = blockIdx.x * blockDim.x + threadIdx.x;
    if (i < n4) {
        float4 v = ((const float4*)x)[i];
        ((__nv_bfloat162*)y)[2 * i + 0] = __floats2bfloat162_rn(v.x, v.y);
        ((__nv_bfloat162*)y)[2 * i + 1] = __floats2bfloat162_rn(v.z, v.w);
    }
}

// tiled transpose: W [DIN][DEMB] f32 -> Wt [DEMB][DIN] bf16
__global__ void k_transpose_w(const float* __restrict__ W, __nv_bfloat16* __restrict__ Wt) {
    __shared__ float tile[32][33];
    int n0 = blockIdx.x * 32, k0 = blockIdx.y * 32;
#pragma unroll
    for (int i = 0; i < 4; i++) {
        int k = k0 + threadIdx.y + i * 8;
        tile[threadIdx.y + i * 8][threadIdx.x] = W[(size_t)k * DEMB + n0 + threadIdx.x];
    }
    __syncthreads();
#pragma unroll
    for (int i = 0; i < 4; i++) {
        int n = n0 + threadIdx.y + i * 8;
        Wt[(size_t)n * DIN + k0 + threadIdx.x] =
            __float2bfloat16(tile[threadIdx.x][threadIdx.y + i * 8]);
    }
}

__global__ void k_supp_stats(const __nv_bfloat16* __restrict__ semb, const int* __restrict__ lab,
                             float* __restrict__ ssum, float* __restrict__ scount) {
    int r = blockIdx.x;
    int L = lab[r];
    if (threadIdx.x == 0) atomicAdd(&scount[L], 1.0f);
    for (int c = threadIdx.x; c < DEMB; c += blockDim.x)
        atomicAdd(&ssum[L * DEMB + c], __bfloat162float(semb[(size_t)r * DEMB + c]));
}

__global__ void k_proto(const float* __restrict__ ssum, const float* __restrict__ scount,
                        const float* __restrict__ qsum, const float* __restrict__ qcount,
                        int useq, __nv_bfloat16* __restrict__ pb, float* __restrict__ pnorm) {
    int c = blockIdx.x;
    float cnt = scount[c] + (useq ? qcount[c] : 0.f);
    float inv = 1.f / fmaxf(cnt, 1.f);
    float s = 0.f;
    for (int j = threadIdx.x; j < DEMB; j += blockDim.x) {
        float p = (ssum[c * DEMB + j] + (useq ? qsum[c * DEMB + j] : 0.f)) * inv;
        __nv_bfloat16 pv = __float2bfloat16(p);
        pb[c * DEMB + j] = pv;
        float pf = __bfloat162float(pv);
        s += pf * pf;
    }
    __shared__ float red[8];
#pragma unroll
    for (int o2 = 16; o2; o2 >>= 1) s += __shfl_xor_sync(~0u, s, o2);
    if ((threadIdx.x & 31) == 0) red[threadIdx.x >> 5] = s;
    __syncthreads();
    if (threadIdx.x < 8) {
        s = red[threadIdx.x];
#pragma unroll
        for (int o2 = 4; o2; o2 >>= 1) s += __shfl_xor_sync(0xff, s, o2);
        if (threadIdx.x == 0) pnorm[c] = s;
    }
}

// segment-sum of query embeddings by label. bfloat162 loads, 2-row unroll into
// two independent smem accumulator banks (breaks the smem RAW chain in half).
// grid (DEMB/256, 32) = 128 blocks, 128 threads, 128KB dynamic smem.
__global__ void __launch_bounds__(128) k_segsum2(const __nv_bfloat16* __restrict__ qemb,
                                                 const int* __restrict__ lab,
                                                 float* __restrict__ qsum) {
    extern __shared__ float sacc[];  // 2 banks * NCLS * 256 floats = 128KB
    const int tid = threadIdx.x;
    for (int i = tid; i < 2 * NCLS * 256; i += 128) sacc[i] = 0.f;
    __syncthreads();
    float* a0 = sacc;
    float* a1 = sacc + NCLS * 256;
    const int colpair = blockIdx.x * 128 + tid;  // bf162 index within a 512-pair row
    const __nv_bfloat162* q2 = (const __nv_bfloat162*)qemb;
    const int rpb = NQRY / gridDim.y;
    const int r0 = blockIdx.y * rpb;
    for (int r = r0; r < r0 + rpb; r += 2) {
        int L0 = __ldg(&lab[r]), L1 = __ldg(&lab[r + 1]);
        float2 v0 = __bfloat1622float2(q2[(size_t)r * 512 + colpair]);
        float2 v1 = __bfloat1622float2(q2[(size_t)(r + 1) * 512 + colpair]);
        float* p0 = &a0[L0 * 256 + tid * 2];
        p0[0] += v0.x; p0[1] += v0.y;
        float* p1 = &a1[L1 * 256 + tid * 2];
        p1[0] += v1.x; p1[1] += v1.y;
    }
    __syncthreads();
    for (int i = tid; i < NCLS * 256; i += 128) {
        int cls = i >> 8, cidx = i & 255;
        atomicAdd(&qsum[cls * DEMB + blockIdx.x * 256 + cidx], a0[i] + a1[i]);
    }
}

// ---------------- bf16 HMMA GEMM (mma.sync m16n8k16), BK=64, 3-stage, swizzled ----------------
// C[M,N] = A[M,K] @ B[N,K]^T
// MODE 0: out_bf16 = C + bias[n]; if qnorm!=null also atomicAdd row sum-of-squares (bf16-rounded)
// MODE 1: labels[m] = argmin_n (pnorm[n] - 2*C), qcount histogram
// MODE 2: outf[m*NCLS+n] = -sqrt(max(qnorm[m]+pnorm[n]-2*C, 1e-12))
#define CP_ASYNC(dst, src) asm volatile("cp.async.cg.shared.global [%0], [%1], 16;\n" ::"r"(dst), "l"(src))

template <int BM, int BN, int WMT, int WNT, int MODE>
__global__ void __launch_bounds__(WMT* WNT * 32, 1) k_gemm(
    const __nv_bfloat16* __restrict__ A, const __nv_bfloat16* __restrict__ B, int K,
    const float* __restrict__ bias, __nv_bfloat16* __restrict__ outb, int ldo,
    const float* __restrict__ pnorm, int* __restrict__ labels, float* __restrict__ qcount,
    float* __restrict__ qnorm, float* __restrict__ outf) {
    constexpr int NT = WMT * WNT * 32;
    constexpr int WM = BM / WMT, WN = BN / WNT;
    constexpr int MF = WM / 16, NF = WN / 8;
    constexpr int AIT = BM * 8 / NT;   // 16B chunks per thread (A)
    constexpr int BIT = BN * 8 / NT;
    constexpr uint32_t STAGE = (BM + BN) * 128;

    extern __shared__ char smem_raw[];
    uint32_t sbase = (uint32_t)__cvta_generic_to_shared(smem_raw);

    const int tid = threadIdx.x;
    const int warp = tid >> 5, lane = tid & 31;
    const int wm = (warp / WNT) * WM, wn = (warp % WNT) * WN;
    const int bm0 = blockIdx.y * BM, bn0 = blockIdx.x * BN;

    const __nv_bfloat16* Ab = A + (size_t)bm0 * K;
    const __nv_bfloat16* Bb = B + (size_t)bn0 * K;

    float acc[MF][NF][4];
#pragma unroll
    for (int i = 0; i < MF; i++)
#pragma unroll
        for (int j = 0; j < NF; j++)
#pragma unroll
            for (int q = 0; q < 4; q++) acc[i][j][q] = 0.f;

    const int KT = K >> 6;  // BK=64

    auto load = [&](int kt) {
        uint32_t sA = sbase + (kt % 3) * STAGE;
        uint32_t sB = sA + (uint32_t)BM * 128u;
        const __nv_bfloat16* Ap = Ab + (size_t)kt * 64;
        const __nv_bfloat16* Bp = Bb + (size_t)kt * 64;
#pragma unroll
        for (int i = 0; i < AIT; i++) {
            int idx = tid + i * NT;
            int r = idx >> 3, c = idx & 7;
            CP_ASYNC(sA + (uint32_t)(r * 128 + ((c ^ (r & 7)) * 16)), Ap + (size_t)r * K + c * 8);
        }
#pragma unroll
        for (int i = 0; i < BIT; i++) {
            int idx = tid + i * NT;
            int r = idx >> 3, c = idx & 7;
            CP_ASYNC(sB + (uint32_t)(r * 128 + ((c ^ (r & 7)) * 16)), Bp + (size_t)r * K + c * 8);
        }
        asm volatile("cp.async.commit_group;\n");
    };

    load(0);
    load(1);
    for (int kt = 0; kt < KT; kt++) {
        if (kt < KT - 1)
            asm volatile("cp.async.wait_group 1;\n" ::: "memory");
        else
            asm volatile("cp.async.wait_group 0;\n" ::: "memory");
        __syncthreads();
        // issue next stage's loads BEFORE compute; writes stage (kt+2)%3 == (kt-1)%3,
        // which every warp finished reading before arriving at the sync above.
        if (kt + 2 < KT) load(kt + 2);
        uint32_t aBase = sbase + (kt % 3) * STAGE;
        uint32_t bBase = aBase + (uint32_t)BM * 128u;
#pragma unroll
        for (int ks = 0; ks < 4; ks++) {
            uint32_t af[MF][4];
#pragma unroll
            for (int mi = 0; mi < MF; mi++) {
                int row = wm + mi * 16 + (lane & 15);
                int ch = (ks * 2 + (lane >> 4)) ^ (row & 7);
                uint32_t adr = aBase + (uint32_t)(row * 128 + ch * 16);
                asm volatile("ldmatrix.sync.aligned.m8n8.x4.shared.b16 {%0,%1,%2,%3},[%4];"
                             : "=r"(af[mi][0]), "=r"(af[mi][1]), "=r"(af[mi][2]), "=r"(af[mi][3])
                             : "r"(adr));
            }
            uint32_t bfr[NF][2];
#pragma unroll
            for (int ni2 = 0; ni2 < NF / 2; ni2++) {
                int nrow = wn + ni2 * 16 + (lane & 7) + ((lane >> 4) << 3);
                int ch = (ks * 2 + ((lane >> 3) & 1)) ^ (nrow & 7);
                uint32_t bd = bBase + (uint32_t)(nrow * 128 + ch * 16);
                uint32_t r0, r1, r2, r3;
                asm volatile("ldmatrix.sync.aligned.m8n8.x4.shared.b16 {%0,%1,%2,%3},[%4];"
                             : "=r"(r0), "=r"(r1), "=r"(r2), "=r"(r3)
                             : "r"(bd));
                bfr[2 * ni2][0] = r0; bfr[2 * ni2][1] = r1;
                bfr[2 * ni2 + 1][0] = r2; bfr[2 * ni2 + 1][1] = r3;
            }
#pragma unroll
            for (int mi = 0; mi < MF; mi++)
#pragma unroll
                for (int ni = 0; ni < NF; ni++)
                    asm volatile(
                        "mma.sync.aligned.m16n8k16.row.col.f32.bf16.bf16.f32 "
                        "{%0,%1,%2,%3},{%4,%5,%6,%7},{%8,%9},{%0,%1,%2,%3};"
                        : "+f"(acc[mi][ni][0]), "+f"(acc[mi][ni][1]),
                          "+f"(acc[mi][ni][2]), "+f"(acc[mi][ni][3])
                        : "r"(af[mi][0]), "r"(af[mi][1]), "r"(af[mi][2]), "r"(af[mi][3]),
                          "r"(bfr[ni][0]), "r"(bfr[ni][1]));
        }
    }

    if (MODE == 0) {
#pragma unroll
        for (int mi = 0; mi < MF; mi++) {
            int row = bm0 + wm + mi * 16 + (lane >> 2);
#pragma unroll
            for (int h = 0; h < 2; h++) {
                int rr = row + h * 8;
                float rs = 0.f;
#pragma unroll
                for (int ni = 0; ni < NF; ni++) {
                    int col = bn0 + wn + ni * 8 + (lane & 3) * 2;
                    float b0v = __ldg(&bias[col]), b1v = __ldg(&bias[col + 1]);
                    __nv_bfloat162 p = __floats2bfloat162_rn(acc[mi][ni][2 * h] + b0v,
                                                             acc[mi][ni][2 * h + 1] + b1v);
                    *(__nv_bfloat162*)(outb + (size_t)rr * ldo + col) = p;
                    if (qnorm) {
                        float x = __bfloat162float(p.x), y = __bfloat162float(p.y);
                        rs += x * x + y * y;
                    }
                }
                if (qnorm) {
                    rs += __shfl_xor_sync(~0u, rs, 1);
                    rs += __shfl_xor_sync(~0u, rs, 2);
                    if ((lane & 3) == 0) atomicAdd(&qnorm[rr], rs);
                }
            }
        }
    } else if (MODE == 1) {
        float bv[MF][2];
        int bc[MF][2];
#pragma unroll
        for (int mi = 0; mi < MF; mi++)
#pragma unroll
            for (int h = 0; h < 2; h++) { bv[mi][h] = 1e30f; bc[mi][h] = 0; }
#pragma unroll
        for (int mi = 0; mi < MF; mi++)
#pragma unroll
            for (int ni = 0; ni < NF; ni++)
#pragma unroll
                for (int h = 0; h < 2; h++)
#pragma unroll
                    for (int j = 0; j < 2; j++) {
                        int c = wn + ni * 8 + (lane & 3) * 2 + j;
                        float m = pnorm[c] - 2.f * acc[mi][ni][2 * h + j];
                        if (m < bv[mi][h]) { bv[mi][h] = m; bc[mi][h] = c; }
                    }
#pragma unroll
        for (int off = 1; off <= 2; off <<= 1)
#pragma unroll
            for (int mi = 0; mi < MF; mi++)
#pragma unroll
                for (int h = 0; h < 2; h++) {
                    float ov = __shfl_xor_sync(~0u, bv[mi][h], off);
                    int oc = __shfl_xor_sync(~0u, bc[mi][h], off);
                    if (ov < bv[mi][h] || (ov == bv[mi][h] && oc < bc[mi][h])) {
                        bv[mi][h] = ov; bc[mi][h] = oc;
                    }
                }
        __syncthreads();  // stages no longer needed; reuse smem for reduction
        float* redv = (float*)smem_raw;
        int* redi = (int*)smem_raw + BM * WNT;
        __shared__ int hist[NCLS];
        if (tid < NCLS) hist[tid] = 0;
        if ((lane & 3) == 0) {
#pragma unroll
            for (int mi = 0; mi < MF; mi++)
#pragma unroll
                for (int h = 0; h < 2; h++) {
                    int r = wm + mi * 16 + (lane >> 2) + 8 * h;
                    redv[r * WNT + (warp % WNT)] = bv[mi][h];
                    redi[r * WNT + (warp % WNT)] = bc[mi][h];
                }
        }
        __syncthreads();
        if (tid < BM) {
            float v = redv[tid * WNT];
            int cbest = redi[tid * WNT];
#pragma unroll
            for (int w2 = 1; w2 < WNT; w2++) {
                float ov = redv[tid * WNT + w2];
                int oc = redi[tid * WNT + w2];
                if (ov < v || (ov == v && oc < cbest)) { v = ov; cbest = oc; }
            }
            labels[bm0 + tid] = cbest;
            atomicAdd(&hist[cbest], 1);
        }
        __syncthreads();
        if (tid < NCLS) atomicAdd(&qcount[tid], (float)hist[tid]);
    } else {  // MODE 2
#pragma unroll
        for (int mi = 0; mi < MF; mi++) {
            int row = bm0 + wm + mi * 16 + (lane >> 2);
#pragma unroll
            for (int h = 0; h < 2; h++) {
                int rr = row + 8 * h;
                float qn = __ldg(&qnorm[rr]);
#pragma unroll
                for (int ni = 0; ni < NF; ni++)
#pragma unroll
                    for (int j = 0; j < 2; j++) {
                        int c = wn + ni * 8 + (lane & 3) * 2 + j;
                        float d2 = qn + pnorm[c] - 2.f * acc[mi][ni][2 * h + j];
                        outf[(size_t)rr * NCLS + c] = -sqrtf(fmaxf(d2, 1e-12f));
                    }
            }
        }
    }
}

// ---------------- host orchestration ----------------
extern "C" void kernel_launch(void* const* d_in, const int* in_sizes, int n_in,
                              void* d_out, int out_size) {
    (void)in_sizes; (void)n_in; (void)out_size;
    const float* support = (const float*)d_in[0];
    const float* query = (const float*)d_in[1];
    const int* slab = (const int*)d_in[2];
    const float* W = (const float*)d_in[3];
    const float* bias = (const float*)d_in[4];
    float* out = (float*)d_out;

    __nv_bfloat16 *Wt, *qx, *sx, *qemb, *semb, *pb;
    float *qnorm, *ssum, *scount, *qsum, *qcount, *pnorm;
    int* labels;
    cudaGetSymbolAddress((void**)&Wt, g_Wt);
    cudaGetSymbolAddress((void**)&qx, g_qx);
    cudaGetSymbolAddress((void**)&sx, g_sx);
    cudaGetSymbolAddress((void**)&qemb, g_qemb);
    cudaGetSymbolAddress((void**)&semb, g_semb);
    cudaGetSymbolAddress((void**)&qnorm, g_qnorm);
    cudaGetSymbolAddress((void**)&ssum, g_ssum);
    cudaGetSymbolAddress((void**)&scount, g_scount);
    cudaGetSymbolAddress((void**)&qsum, g_qsum);
    cudaGetSymbolAddress((void**)&qcount, g_qcount);
    cudaGetSymbolAddress((void**)&pb, g_pb);
    cudaGetSymbolAddress((void**)&pnorm, g_pnorm);
    cudaGetSymbolAddress((void**)&labels, g_labels);

    const int SMEM_BIG = 3 * (128 + 256) * 128;   // 147456
    const int SMEM_SML = 3 * (128 + 64) * 128;    // 73728
    const int SMEM_SEG = 2 * NCLS * 256 * 4;      // 131072
    cudaFuncSetAttribute(k_gemm<128, 256, 2, 4, 0>, cudaFuncAttributeMaxDynamicSharedMemorySize, SMEM_BIG);
    cudaFuncSetAttribute(k_gemm<128, 64, 4, 2, 1>, cudaFuncAttributeMaxDynamicSharedMemorySize, SMEM_SML);
    cudaFuncSetAttribute(k_gemm<128, 64, 4, 2, 2>, cudaFuncAttributeMaxDynamicSharedMemorySize, SMEM_SML);
    cudaFuncSetAttribute(k_segsum2, cudaFuncAttributeMaxDynamicSharedMemorySize, SMEM_SEG);

    // conversions
    k_transpose_w<<<dim3(DEMB / 32, DIN / 32), dim3(32, 8)>>>(W, Wt);
    k_convert<<<(NSUP * DIN / 4 + 255) / 256, 256>>>(support, sx, NSUP * DIN / 4);
    k_convert<<<(NQRY * DIN / 4 + 255) / 256, 256>>>(query, qx, NQRY * DIN / 4);

    // embeddings (bf16 out, bias fused; query also accumulates qnorm)
    k_zero<<<(NQRY + 255) / 256, 256>>>(qnorm, NQRY);
    k_gemm<128, 256, 2, 4, 0><<<dim3(DEMB / 256, NSUP / 128), 256, SMEM_BIG>>>(
        sx, Wt, DIN, bias, semb, DEMB, nullptr, nullptr, nullptr, nullptr, nullptr);
    k_gemm<128, 256, 2, 4, 0><<<dim3(DEMB / 256, NQRY / 128), 256, SMEM_BIG>>>(
        qx, Wt, DIN, bias, qemb, DEMB, nullptr, nullptr, nullptr, qnorm, nullptr);

    // support class sums + counts -> initial prototypes
    k_zero<<<(NCLS * DEMB + 255) / 256, 256>>>(ssum, NCLS * DEMB);
    k_zero<<<1, 64>>>(scount, NCLS);
    k_supp_stats<<<NSUP, 256>>>(semb, slab, ssum, scount);
    k_proto<<<NCLS, 256>>>(ssum, scount, nullptr, nullptr, 0, pb, pnorm);

    for (int s = 0; s < NSTEPS; s++) {
        k_zero<<<(NCLS * DEMB + 255) / 256, 256>>>(qsum, NCLS * DEMB);
        k_zero<<<1, 64>>>(qcount, NCLS);
        k_gemm<128, 64, 4, 2, 1><<<dim3(1, NQRY / 128), 256, SMEM_SML>>>(
            qemb, pb, DEMB, nullptr, nullptr, 0, pnorm, labels, qcount, nullptr, nullptr);
        k_segsum2<<<dim3(DEMB / 256, 32), 128, SMEM_SEG>>>(qemb, labels, qsum);
        k_proto<<<NCLS, 256>>>(ssum, scount, qsum, qcount, 1, pb, pnorm);
    }

    // final logits
    k_gemm<128, 64, 4, 2, 2><<<dim3(1, NQRY / 128), 256, SMEM_SML>>>(
        qemb, pb, DEMB, nullptr, nullptr, 0, pnorm, nullptr, nullptr, qnorm, out);
}